// round 8
// baseline (speedup 1.0000x reference)
#include <cuda_runtime.h>
#include <cstdint>
#include <cstddef>

#define SEQ   2048
#define BATCH 128
#define HID   256
#define NCTA  128   // 64 clusters * 2 CTAs

// ---------------- f32x2 packed helpers (sm_103a) ----------------
__device__ __forceinline__ unsigned long long pk2(float x, float y){
    unsigned long long r; asm("mov.b64 %0, {%1,%2};" : "=l"(r) : "f"(x), "f"(y)); return r;
}
__device__ __forceinline__ void upk2(unsigned long long v, float& x, float& y){
    asm("mov.b64 {%0,%1}, %2;" : "=f"(x), "=f"(y) : "l"(v));
}
__device__ __forceinline__ unsigned long long ffma2(unsigned long long a,
                                                    unsigned long long b,
                                                    unsigned long long c){
    unsigned long long d;
    asm("fma.rn.f32x2 %0, %1, %2, %3;" : "=l"(d) : "l"(a), "l"(b), "l"(c));
    return d;
}

// ---------------- smem / cluster helpers (all proven in the R5 passing kernel) ----
__device__ __forceinline__ unsigned smem_u32(const void* p){
    return (unsigned)__cvta_generic_to_shared(p);
}
__device__ __forceinline__ unsigned mapa_u32(unsigned laddr, unsigned peer){
    unsigned r;
    asm("mapa.shared::cluster.u32 %0, %1, %2;" : "=r"(r) : "r"(laddr), "r"(peer));
    return r;
}
__device__ __forceinline__ void mbar_init(unsigned a, unsigned cnt){
    asm volatile("mbarrier.init.shared.b64 [%0], %1;" :: "r"(a), "r"(cnt) : "memory");
}
__device__ __forceinline__ void mbar_inval(unsigned a){
    asm volatile("mbarrier.inval.shared.b64 [%0];" :: "r"(a) : "memory");
}
__device__ __forceinline__ void st_remote_f(unsigned raddr, float v){
    asm volatile("st.shared::cluster.b32 [%0], %1;" :: "r"(raddr), "f"(v) : "memory");
}
__device__ __forceinline__ void arrive_remote(unsigned raddr){
    asm volatile("mbarrier.arrive.release.cluster.shared::cluster.b64 _, [%0];"
                 :: "r"(raddr) : "memory");
}
__device__ __forceinline__ void mbar_wait_acq_cluster(unsigned a, unsigned parity){
    asm volatile(
        "{\n\t.reg .pred P;\n\t"
        "WL_%=:\n\t"
        "mbarrier.try_wait.parity.acquire.cluster.shared::cta.b64 P, [%0], %1, 0x989680;\n\t"
        "@!P bra WL_%=;\n\t"
        "}"
        :: "r"(a), "r"(parity) : "memory");
}
__device__ __forceinline__ void cluster_sync_hw(){
    asm volatile("barrier.cluster.arrive.aligned;" ::: "memory");
    asm volatile("barrier.cluster.wait.aligned;"   ::: "memory");
}
__device__ __forceinline__ unsigned cta_rank(){
    unsigned r; asm("mov.u32 %0, %%cluster_ctarank;" : "=r"(r)); return r;
}
__device__ __forceinline__ float sigmoidf(float x){
    return __fdividef(1.f, 1.f + __expf(-x));
}

// =====================================================================
// Persistent RNN: 64 clusters x 2 CTAs, 2 batch rows per cluster.
// CTA r holds W_eff[all 256 rows][cols r*128 .. r*128+127]:
//   thread t owns output row t (128 weights -> 64 f32x2 regs).
// Per step: every thread FFMAs its row over the LOCALLY-produced a-half.
//   Rows in the peer's half (senders): ship partial via st.shared::cluster,
//     then ONE lane-elected remote arrive per warp (4 arrives/slot, no storm).
//   Rows in own half (receivers): wait (cluster-acquire), add peer partial,
//     sigmoid, store h, write new activation locally.
// The partials are consumed AFTER the 512-cycle FFMA block, so DSMEM
// latency overlaps compute; batch-0 is shipped at the loop midpoint.
// =====================================================================
__global__ void __cluster_dims__(2,1,1) __launch_bounds__(256,1)
rnn_kernel(const float* __restrict__ x,      // (SEQ, BATCH)
           const float* __restrict__ h0,     // (BATCH, HID)
           const float* __restrict__ W_ih,   // (HID, 1)
           const float* __restrict__ W_hh,   // (HID, HID)
           const float* __restrict__ W_hhb,  // (HID, HID)
           const float* __restrict__ b_h,    // (HID,)
           const void*  __restrict__ ctxp,   // scalar
           float* __restrict__ outbuf)       // (BATCH, SEQ, HID)
{
    __shared__ __align__(16) float sa[2][2][128];    // [parity][batch][j-local]  2KB
    __shared__ __align__(16) float rbuf[2][2][128];  // [parity][batch][iloc]     2KB
    __shared__ float sx[SEQ * 2];                    // x[t][b0..b1]             16KB
    __shared__ __align__(8) unsigned long long mb[4];// slot = parity*2 + batch

    const int t        = (int)threadIdx.x;
    const unsigned rank = cta_rank();
    const unsigned peer = rank ^ 1u;
    const int cid   = (int)blockIdx.x >> 1;
    const int b0    = cid * 2;
    const int b1    = b0 + 1;
    const int iloc  = t & 127;
    const int tseg  = t >> 7;
    const int jbase = (int)rank << 7;            // my j-half (columns)
    const bool is_recv = (tseg == (int)rank);    // rows I finalize
    const bool lane0   = ((t & 31) == 0);

    float ctx;
    {
        int   iv = *(const int*)ctxp;
        float fv = *(const float*)ctxp;
        ctx = (iv >= -1000000 && iv <= 1000000) ? (float)iv : fv;
    }

    // ---- weights: row t, my 128-column half, packed f32x2 ----
    unsigned long long wreg[64];
    {
        const float4* wh = reinterpret_cast<const float4*>(W_hh  + (size_t)t * HID + jbase);
        const float4* wb = reinterpret_cast<const float4*>(W_hhb + (size_t)t * HID + jbase);
        #pragma unroll
        for (int m = 0; m < 32; ++m){
            float4 a4 = wh[m];
            float4 c4 = wb[m];
            wreg[2*m]   = pk2(fmaf(ctx, c4.x, a4.x), fmaf(ctx, c4.y, a4.y));
            wreg[2*m+1] = pk2(fmaf(ctx, c4.z, a4.z), fmaf(ctx, c4.w, a4.w));
        }
    }
    const float win_r = W_ih[t];
    const float bh_r  = b_h[t];

    // ---- preload x columns for b0/b1 ----
    for (int idx = t; idx < SEQ * 2; idx += 256){
        sx[idx] = x[(size_t)(idx >> 1) * BATCH + b0 + (idx & 1)];
    }
    // ---- init a(h0) for my j-half: threads t<128 -> batch0, t>=128 -> batch1 ----
    sa[0][tseg][iloc] = fmaf(2.f, h0[(size_t)(tseg ? b1 : b0) * HID + jbase + iloc], -1.f);

    // ---- mbarriers: count = 4 (one elected arrive per sender warp) ----
    const unsigned mb_l = smem_u32(&mb[0]);
    if (t == 0){
        #pragma unroll
        for (int s = 0; s < 4; ++s) mbar_init(mb_l + s*8, 4);
    }
    __syncthreads();
    cluster_sync_hw();   // peer's mbars/buffers initialized before any send

    const unsigned rb_r = mapa_u32(smem_u32(&rbuf[0][0][0]), peer) + (unsigned)(iloc * 4);
    const unsigned mb_r = mapa_u32(mb_l, peer);

    float* outp0 = outbuf + (size_t)b0 * SEQ * HID + t;  // t = global row (recv only)
    float* outp1 = outbuf + (size_t)b1 * SEQ * HID + t;

    int php0 = 0, php1 = 0;   // wait parity per step-parity class

    for (int step = 0; step < SEQ; ++step){
        const int pi  = step & 1;
        const int nxt = pi ^ 1;
        const unsigned slot = (unsigned)(pi * 2);

        // ---- batch 0: FFMA over my j-half (64 f32x2) ----
        float p0;
        {
            const ulonglong2* ap = reinterpret_cast<const ulonglong2*>(&sa[pi][0][0]);
            unsigned long long acc0 = 0ull, acc1 = 0ull;
            #pragma unroll
            for (int m = 0; m < 32; ++m){
                ulonglong2 A = ap[m];
                acc0 = ffma2(wreg[2*m],   A.x, acc0);
                acc1 = ffma2(wreg[2*m+1], A.y, acc1);
            }
            float qa, qb, qc, qd;
            upk2(acc0, qa, qb); upk2(acc1, qc, qd);
            p0 = (qa + qb) + (qc + qd);
        }
        if (!is_recv){   // ship early: latency hides behind batch-1 FFMA
            st_remote_f(rb_r + slot * 512u, p0);
            __syncwarp();
            if (lane0) arrive_remote(mb_r + slot * 8u);
        }

        // ---- batch 1 ----
        float p1;
        {
            const ulonglong2* ap = reinterpret_cast<const ulonglong2*>(&sa[pi][1][0]);
            unsigned long long acc0 = 0ull, acc1 = 0ull;
            #pragma unroll
            for (int m = 0; m < 32; ++m){
                ulonglong2 A = ap[m];
                acc0 = ffma2(wreg[2*m],   A.x, acc0);
                acc1 = ffma2(wreg[2*m+1], A.y, acc1);
            }
            float qa, qb, qc, qd;
            upk2(acc0, qa, qb); upk2(acc1, qc, qd);
            p1 = (qa + qb) + (qc + qd);
        }
        if (!is_recv){
            st_remote_f(rb_r + (slot + 1u) * 512u, p1);
            __syncwarp();
            if (lane0) arrive_remote(mb_r + (slot + 1u) * 8u);
        }

        if (is_recv){
            const int myph = pi ? php1 : php0;
            // batch 0: wait (usually already complete), finalize, store
            mbar_wait_acq_cluster(mb_l + slot * 8u, (unsigned)myph);
            float pre0 = p0 + rbuf[pi][0][iloc] + fmaf(sx[2*step],     win_r, bh_r);
            float h0v  = sigmoidf(pre0);
            outp0[(size_t)step * HID] = h0v;
            sa[nxt][0][iloc] = fmaf(2.f, h0v, -1.f);
            // batch 1
            mbar_wait_acq_cluster(mb_l + (slot + 1u) * 8u, (unsigned)myph);
            float pre1 = p1 + rbuf[pi][1][iloc] + fmaf(sx[2*step + 1], win_r, bh_r);
            float h1v  = sigmoidf(pre1);
            outp1[(size_t)step * HID] = h1v;
            sa[nxt][1][iloc] = fmaf(2.f, h1v, -1.f);
            if (pi) php1 ^= 1; else php0 ^= 1;
        }
        __syncthreads();   // new a-half visible to senders; rbuf slot free
    }

    cluster_sync_hw();   // no CTA exits while peer may still touch our smem
    if (t == 0){
        #pragma unroll
        for (int s = 0; s < 4; ++s) mbar_inval(mb_l + s*8);
    }
}

// =====================================================================
// y[b,t] = out[b,t,:] . W[0,:] + b[0]   (one warp per (b,t) row)
// =====================================================================
__global__ void __launch_bounds__(256)
y_kernel(const float* __restrict__ outbuf,  // (BATCH, SEQ, HID)
         const float* __restrict__ W,       // (2, HID) -> row 0
         const float* __restrict__ bb,      // (2,)
         float* __restrict__ y)             // (BATCH, SEQ)
{
    int row  = (int)blockIdx.x * 8 + ((int)threadIdx.x >> 5);
    int lane = (int)threadIdx.x & 31;
    const float4* p  = reinterpret_cast<const float4*>(outbuf + (size_t)row * HID);
    const float4* wp = reinterpret_cast<const float4*>(W);
    float4 a = p[lane*2],  b4 = p[lane*2 + 1];
    float4 u = wp[lane*2], v  = wp[lane*2 + 1];
    float s = a.x*u.x + a.y*u.y + a.z*u.z + a.w*u.w
            + b4.x*v.x + b4.y*v.y + b4.z*v.z + b4.w*v.w;
    #pragma unroll
    for (int off = 16; off; off >>= 1) s += __shfl_xor_sync(0xFFFFFFFFu, s, off);
    if (lane == 0) y[row] = s + bb[0];
}

extern "C" void kernel_launch(void* const* d_in, const int* in_sizes, int n_in,
                              void* d_out, int out_size)
{
    const float* x     = (const float*)d_in[0];
    const float* h0    = (const float*)d_in[1];
    const float* W_ih  = (const float*)d_in[2];
    const float* W_hh  = (const float*)d_in[3];
    const float* W_hhb = (const float*)d_in[4];
    const float* b_h   = (const float*)d_in[5];
    const float* W     = (const float*)d_in[6];
    const float* b     = (const float*)d_in[7];
    const void*  ctx   = d_in[8];

    float* y      = (float*)d_out;                       // (BATCH, SEQ)
    float* outbuf = y + (size_t)BATCH * SEQ;             // (BATCH, SEQ, HID)

    rnn_kernel<<<NCTA, 256>>>(x, h0, W_ih, W_hh, W_hhb, b_h, ctx, outbuf);
    y_kernel<<<(BATCH * SEQ) / 8, 256>>>(outbuf, W, b, y);
}

// round 11
// speedup vs baseline: 1.2614x; 1.2614x over previous
#include <cuda_runtime.h>
#include <cstdint>
#include <cstddef>

#define SEQ   2048
#define BATCH 128
#define HID   256
#define NCTA  128   // 64 clusters * 2 CTAs

// ---------------- f32x2 packed helpers (sm_103a) ----------------
__device__ __forceinline__ unsigned long long pk2(float x, float y){
    unsigned long long r; asm("mov.b64 %0, {%1,%2};" : "=l"(r) : "f"(x), "f"(y)); return r;
}
__device__ __forceinline__ void upk2(unsigned long long v, float& x, float& y){
    asm("mov.b64 {%0,%1}, %2;" : "=f"(x), "=f"(y) : "l"(v));
}
__device__ __forceinline__ unsigned long long ffma2(unsigned long long a,
                                                    unsigned long long b,
                                                    unsigned long long c){
    unsigned long long d;
    asm("fma.rn.f32x2 %0, %1, %2, %3;" : "=l"(d) : "l"(a), "l"(b), "l"(c));
    return d;
}

// ---------------- smem / cluster helpers (proven in R5/R8 passing kernels) ----
__device__ __forceinline__ unsigned smem_u32(const void* p){
    return (unsigned)__cvta_generic_to_shared(p);
}
__device__ __forceinline__ unsigned mapa_u32(unsigned laddr, unsigned peer){
    unsigned r;
    asm("mapa.shared::cluster.u32 %0, %1, %2;" : "=r"(r) : "r"(laddr), "r"(peer));
    return r;
}
__device__ __forceinline__ void mbar_init(unsigned a, unsigned cnt){
    asm volatile("mbarrier.init.shared.b64 [%0], %1;" :: "r"(a), "r"(cnt) : "memory");
}
__device__ __forceinline__ void mbar_inval(unsigned a){
    asm volatile("mbarrier.inval.shared.b64 [%0];" :: "r"(a) : "memory");
}
__device__ __forceinline__ void st_remote_f(unsigned raddr, float v){
    asm volatile("st.shared::cluster.b32 [%0], %1;" :: "r"(raddr), "f"(v) : "memory");
}
__device__ __forceinline__ void arrive_remote(unsigned raddr){
    asm volatile("mbarrier.arrive.release.cluster.shared::cluster.b64 _, [%0];"
                 :: "r"(raddr) : "memory");
}
__device__ __forceinline__ void mbar_wait_acq_cluster(unsigned a, unsigned parity){
    asm volatile(
        "{\n\t.reg .pred P;\n\t"
        "WL_%=:\n\t"
        "mbarrier.try_wait.parity.acquire.cluster.shared::cta.b64 P, [%0], %1, 0x989680;\n\t"
        "@!P bra WL_%=;\n\t"
        "}"
        :: "r"(a), "r"(parity) : "memory");
}
__device__ __forceinline__ void cluster_sync_hw(){
    asm volatile("barrier.cluster.arrive.aligned;" ::: "memory");
    asm volatile("barrier.cluster.wait.aligned;"   ::: "memory");
}
__device__ __forceinline__ unsigned cta_rank(){
    unsigned r; asm("mov.u32 %0, %%cluster_ctarank;" : "=r"(r)); return r;
}
__device__ __forceinline__ float sigmoidf(float x){
    return __fdividef(1.f, 1.f + __expf(-x));
}

// =====================================================================
// Persistent RNN (R5 structure): 64 clusters x 2 CTAs, 2 batches/cluster.
// CTA r holds W_eff rows [r*128, r*128+128) x all 256 cols, reg-resident:
//   thread t: iloc = t&127 (row within half), jseg = t>>7 (col half).
// Per step: FFMA partials over (row iloc, col-half jseg) for both batches
//   -> part[jseg][batch][iloc] -> B1 -> epilogue on ALL 256 threads
//   (thread t finalizes batch t>>7, row iloc): sigmoid, STG h, write local
//   activation, ship one activation to peer, per-warp elected release-arrive
//   -> B2 -> threads whose j-half is peer-produced wait (overlapped; the
//   peer's fabric latency hides behind our epilogue + barriers).
// =====================================================================
__global__ void __cluster_dims__(2,1,1) __launch_bounds__(256,1)
rnn_kernel(const float* __restrict__ x,      // (SEQ, BATCH)
           const float* __restrict__ h0,     // (BATCH, HID)
           const float* __restrict__ W_ih,   // (HID, 1)
           const float* __restrict__ W_hh,   // (HID, HID)
           const float* __restrict__ W_hhb,  // (HID, HID)
           const float* __restrict__ b_h,    // (HID,)
           const void*  __restrict__ ctxp,   // scalar
           float* __restrict__ outbuf)       // (BATCH, SEQ, HID)
{
    __shared__ __align__(16) float sa[2][2][HID];      // [buf][batch][j]   4 KB
    __shared__ __align__(16) float part[2][2][128];    // [jseg][batch][iloc] 2 KB
    __shared__ float sx[SEQ * 2];                      // x[t][b0..b1]     16 KB
    __shared__ __align__(8) unsigned long long mbar[2];

    const int t    = (int)threadIdx.x;
    const unsigned rank = cta_rank();
    const unsigned peer = rank ^ 1u;
    const int cid  = (int)blockIdx.x >> 1;
    const int b0   = cid * 2;
    const int iloc = t & 127;
    const int jseg = t >> 7;          // FFMA: column half; epilogue: batch select
    const int iglob = ((int)rank << 7) + iloc;
    const int jb   = jseg << 7;

    float ctx;
    {
        int   iv = *(const int*)ctxp;
        float fv = *(const float*)ctxp;
        ctx = (iv >= -1000000 && iv <= 1000000) ? (float)iv : fv;
    }

    // ---- load W_eff (row iglob, col-half jb) into registers, f32x2-packed ----
    unsigned long long wreg[64];
    {
        const float4* wh = reinterpret_cast<const float4*>(W_hh  + (size_t)iglob * HID + jb);
        const float4* wb = reinterpret_cast<const float4*>(W_hhb + (size_t)iglob * HID + jb);
        #pragma unroll
        for (int m = 0; m < 32; ++m){
            float4 a4 = wh[m];
            float4 c4 = wb[m];
            wreg[2*m]   = pk2(fmaf(ctx, c4.x, a4.x), fmaf(ctx, c4.y, a4.y));
            wreg[2*m+1] = pk2(fmaf(ctx, c4.z, a4.z), fmaf(ctx, c4.w, a4.w));
        }
    }
    const float win_r = W_ih[iglob];
    const float bh_r  = b_h[iglob];

    // ---- preload x columns for b0/b1 ----
    for (int idx = t; idx < SEQ * 2; idx += 256){
        sx[idx] = x[(size_t)(idx >> 1) * BATCH + b0 + (idx & 1)];
    }
    // ---- init activation buffer 0 from h0 (full vector, both batches) ----
    {
        int j = t;  // 256 threads, HID = 256
        sa[0][0][j] = fmaf(2.f, h0[(size_t)b0 * HID + j], -1.f);
        sa[0][1][j] = fmaf(2.f, h0[(size_t)(b0 + 1) * HID + j], -1.f);
    }
    if (t == 0){
        mbar_init(smem_u32(&mbar[0]), 8);   // 8 warps, one elected arrive each
        mbar_init(smem_u32(&mbar[1]), 8);
    }
    __syncthreads();
    cluster_sync_hw();   // mbar init + buffers visible cluster-wide

    // epilogue role: batch bsel = jseg, row iglob
    float* outp = outbuf + (size_t)(b0 + jseg) * SEQ * HID + iglob;

    const unsigned sa_u32   = smem_u32(&sa[0][0][0]);
    const unsigned mbar_u32 = smem_u32(&mbar[0]);
    // remote dst for my shipped activation: peer's sa[nxt][jseg(batch)][iglob]
    const unsigned ra_base  = mapa_u32(sa_u32, peer)
                            + (unsigned)((jseg * HID + iglob) * 4);
    const unsigned mbar_r   = mapa_u32(mbar_u32, peer);
    const bool iwait = (jseg != (int)rank);   // my FFMA j-half is peer-produced
    const bool lane0 = ((t & 31) == 0);
    int ph[2] = {0, 0};
    int cur = 0;

    for (int step = 0; step < SEQ; ++step){
        const int nxt = cur ^ 1;

        // ---- matvec partials over my j-half, both batches, f32x2-packed ----
        const ulonglong2* a0p = reinterpret_cast<const ulonglong2*>(&sa[cur][0][jb]);
        const ulonglong2* a1p = reinterpret_cast<const ulonglong2*>(&sa[cur][1][jb]);
        unsigned long long acc00 = 0ull, acc01 = 0ull, acc10 = 0ull, acc11 = 0ull;
        #pragma unroll
        for (int m = 0; m < 32; ++m){
            ulonglong2 A0 = a0p[m];
            ulonglong2 A1 = a1p[m];
            acc00 = ffma2(wreg[2*m],   A0.x, acc00);
            acc01 = ffma2(wreg[2*m+1], A0.y, acc01);
            acc10 = ffma2(wreg[2*m],   A1.x, acc10);
            acc11 = ffma2(wreg[2*m+1], A1.y, acc11);
        }
        float s0a, s0b, s0c, s0d, s1a, s1b, s1c, s1d;
        upk2(acc00, s0a, s0b); upk2(acc01, s0c, s0d);
        upk2(acc10, s1a, s1b); upk2(acc11, s1c, s1d);
        part[jseg][0][iloc] = (s0a + s0b) + (s0c + s0d);
        part[jseg][1][iloc] = (s1a + s1b) + (s1c + s1d);
        __syncthreads();   // B1: partials ready; everyone done reading sa[cur]

        // ---- epilogue: ALL threads; thread t -> batch jseg, row iglob ----
        {
            float pre = part[0][jseg][iloc] + part[1][jseg][iloc]
                      + fmaf(sx[2*step + jseg], win_r, bh_r);
            float hv = sigmoidf(pre);
            outp[(size_t)step * HID] = hv;
            float av = fmaf(2.f, hv, -1.f);
            sa[nxt][jseg][iglob] = av;                       // local copy
            st_remote_f(ra_base + (unsigned)(nxt * 2048), av); // peer copy
            __syncwarp();
            if (lane0) arrive_remote(mbar_r + (unsigned)(nxt * 8));
        }
        __syncthreads();   // B2: local half of sa[nxt] visible; part reusable

        if (iwait){
            mbar_wait_acq_cluster(mbar_u32 + (unsigned)(nxt * 8), (unsigned)ph[nxt]);
            ph[nxt] ^= 1;
        }
        cur = nxt;
    }

    cluster_sync_hw();   // no CTA exits while peer may still write our smem
    if (t == 0){ mbar_inval(smem_u32(&mbar[0])); mbar_inval(smem_u32(&mbar[1])); }
}

// =====================================================================
// y[b,t] = out[b,t,:] . W[0,:] + b[0]   (one warp per (b,t) row)
// =====================================================================
__global__ void __launch_bounds__(256)
y_kernel(const float* __restrict__ outbuf,  // (BATCH, SEQ, HID)
         const float* __restrict__ W,       // (2, HID) -> row 0
         const float* __restrict__ bb,      // (2,)
         float* __restrict__ y)             // (BATCH, SEQ)
{
    int row  = (int)blockIdx.x * 8 + ((int)threadIdx.x >> 5);
    int lane = (int)threadIdx.x & 31;
    const float4* p  = reinterpret_cast<const float4*>(outbuf + (size_t)row * HID);
    const float4* wp = reinterpret_cast<const float4*>(W);
    float4 a = p[lane*2],  b4 = p[lane*2 + 1];
    float4 u = wp[lane*2], v  = wp[lane*2 + 1];
    float s = a.x*u.x + a.y*u.y + a.z*u.z + a.w*u.w
            + b4.x*v.x + b4.y*v.y + b4.z*v.z + b4.w*v.w;
    #pragma unroll
    for (int off = 16; off; off >>= 1) s += __shfl_xor_sync(0xFFFFFFFFu, s, off);
    if (lane == 0) y[row] = s + bb[0];
}

extern "C" void kernel_launch(void* const* d_in, const int* in_sizes, int n_in,
                              void* d_out, int out_size)
{
    const float* x     = (const float*)d_in[0];
    const float* h0    = (const float*)d_in[1];
    const float* W_ih  = (const float*)d_in[2];
    const float* W_hh  = (const float*)d_in[3];
    const float* W_hhb = (const float*)d_in[4];
    const float* b_h   = (const float*)d_in[5];
    const float* W     = (const float*)d_in[6];
    const float* b     = (const float*)d_in[7];
    const void*  ctx   = d_in[8];

    float* y      = (float*)d_out;                       // (BATCH, SEQ)
    float* outbuf = y + (size_t)BATCH * SEQ;             // (BATCH, SEQ, HID)

    rnn_kernel<<<NCTA, 256>>>(x, h0, W_ih, W_hh, W_hhb, b_h, ctx, outbuf);
    y_kernel<<<(BATCH * SEQ) / 8, 256>>>(outbuf, W, b, y);
}